// round 1
// baseline (speedup 1.0000x reference)
#include <cuda_runtime.h>
#include <cuda_bf16.h>

// Problem dims (fixed by the dataset)
#define BB 4
#define CC 32
#define HH 64
#define WW 64
#define KK 64
#define HW 4096          // H*W
#define CAPK 1152        // max nnz per RF (disk r<=17.2 -> <=~1030)

// ---------- static device scratch (no allocations allowed) ----------
__device__ unsigned short g_kcoords[KK * CAPK]; // k-major: pixel index per entry
__device__ float          g_kvals  [KK * CAPK]; // k-major: rf value per entry
__device__ int            g_knnz   [KK];        // entries per k
__device__ unsigned char  g_pk     [KK * HW];   // px-major: k id, layout [j][px]
__device__ float          g_pval   [KK * HW];   // px-major: rf value, layout [j][px]
__device__ int            g_pcnt   [HW];        // k-count per pixel

// ============================================================================
// Prep kernel: 80 blocks x 256 threads.
//   blocks 0..63  : k-major compaction of rfs[k] (deterministic order)
//   blocks 64..79 : pixel-major compaction (deterministic k order per pixel)
// ============================================================================
__global__ void rf_prep_kernel(const float* __restrict__ rfs)
{
    int tid = threadIdx.x;
    if (blockIdx.x < KK) {
        // ---- k-major compaction for k = blockIdx.x ----
        int k = blockIdx.x;
        const float* r = rfs + k * HW;
        __shared__ int s[256];
        // each thread owns 16 contiguous pixels
        int px0 = tid * 16;
        int cnt = 0;
        #pragma unroll
        for (int j = 0; j < 16; j++) cnt += (r[px0 + j] > 0.0f);
        s[tid] = cnt;
        __syncthreads();
        // inclusive Hillis-Steele scan over 256
        for (int off = 1; off < 256; off <<= 1) {
            int add = (tid >= off) ? s[tid - off] : 0;
            __syncthreads();
            s[tid] += add;
            __syncthreads();
        }
        int off = s[tid] - cnt;            // exclusive offset
        int total = s[255];
        unsigned short* cp = g_kcoords + k * CAPK;
        float*          vp = g_kvals   + k * CAPK;
        #pragma unroll
        for (int j = 0; j < 16; j++) {
            float g = r[px0 + j];
            if (g > 0.0f) {
                if (off < CAPK) {
                    cp[off] = (unsigned short)(px0 + j);
                    vp[off] = g;
                }
                off++;
            }
        }
        if (tid == 0) g_knnz[k] = (total < CAPK) ? total : CAPK;
    } else {
        // ---- pixel-major compaction ----
        int px = (blockIdx.x - KK) * 256 + tid;   // 16 blocks x 256 = 4096
        int cnt = 0;
        #pragma unroll 8
        for (int k = 0; k < KK; k++) {
            float g = rfs[k * HW + px];           // coalesced across lanes
            if (g > 0.0f) {
                g_pk  [cnt * HW + px] = (unsigned char)k;
                g_pval[cnt * HW + px] = g;
                cnt++;
            }
        }
        g_pcnt[px] = cnt;
    }
}

// ============================================================================
// Main kernel: one block per (b,c) image. 256 threads = 8 warps.
//   Phase A: per-k denominators via warp reductions (k-major lists)
//   Phase B: per-pixel h accumulation (pixel-major lists, race-free)
//   Phase C: 2x2 block-max pooling, write output
// ============================================================================
__global__ void __launch_bounds__(256, 1)
rf_pool_main_kernel(const float* __restrict__ u, float* __restrict__ out)
{
    __shared__ float u_s[HW];     // 16 KB
    __shared__ float h_s[HW];     // 16 KB
    __shared__ float invd_s[KK];  // 256 B

    int tid  = threadIdx.x;
    int warp = tid >> 5;
    int lane = tid & 31;

    // load this image into smem (coalesced float4)
    const float4* u4 = (const float4*)(u + (size_t)blockIdx.x * HW);
    #pragma unroll
    for (int i = 0; i < HW / 4 / 256; i++)
        ((float4*)u_s)[tid + i * 256] = u4[tid + i * 256];
    __syncthreads();

    // ---- Phase A: denom[k] = 1 + sum_supp exp(u*rf) ----
    for (int k = warp; k < KK; k += 8) {
        int n = g_knnz[k];
        const unsigned short* cp = g_kcoords + k * CAPK;
        const float*          vp = g_kvals   + k * CAPK;
        float s = 0.0f;
        #pragma unroll 4
        for (int i = lane; i < n; i += 32) {
            int c = cp[i];
            s += __expf(u_s[c] * vp[i]);
        }
        #pragma unroll
        for (int o = 16; o; o >>= 1) s += __shfl_xor_sync(0xffffffffu, s, o);
        if (lane == 0) invd_s[k] = 1.0f / (1.0f + s);
    }
    __syncthreads();

    // ---- Phase B: h[px] = sum_j exp(u[px]*val_j) * invd[k_j] ----
    #pragma unroll
    for (int r = 0; r < HW / 256; r++) {
        int px = tid + r * 256;
        float uv  = u_s[px];
        int  cnt  = g_pcnt[px];
        float h = 0.0f;
        #pragma unroll 4
        for (int j = 0; j < cnt; j++) {
            float val = g_pval[j * HW + px];   // coalesced across lanes
            int   k   = g_pk  [j * HW + px];
            h += __expf(uv * val) * invd_s[k];
        }
        h_s[px] = h;
    }
    __syncthreads();

    // ---- Phase C: 2x2 block max -> 32x32 outputs ----
    float* o = out + (size_t)blockIdx.x * 1024;
    #pragma unroll
    for (int r = 0; r < 1024 / 256; r++) {
        int oi = tid + r * 256;
        int oy = oi >> 5, ox = oi & 31;
        int p0 = (oy * 2) * WW + ox * 2;
        float m = fmaxf(fmaxf(h_s[p0], h_s[p0 + 1]),
                        fmaxf(h_s[p0 + WW], h_s[p0 + WW + 1]));
        o[oi] = m;
    }
}

// ============================================================================
extern "C" void kernel_launch(void* const* d_in, const int* in_sizes, int n_in,
                              void* d_out, int out_size)
{
    // inputs: u (4*32*64*64 = 524288 f32), rfs (64*64*64 = 262144 f32)
    const float* u   = (const float*)d_in[0];
    const float* rfs = (const float*)d_in[1];
    if (n_in >= 2 && in_sizes[0] == KK * HW && in_sizes[1] == BB * CC * HW) {
        // defensive: swapped order
        const float* t = u; u = rfs; rfs = t;
    }
    float* out = (float*)d_out;

    rf_prep_kernel<<<KK + HW / 256, 256>>>(rfs);
    rf_pool_main_kernel<<<BB * CC, 256>>>(u, out);
}

// round 4
// speedup vs baseline: 2.5637x; 2.5637x over previous
#include <cuda_runtime.h>
#include <cuda_bf16.h>

// Problem dims (fixed by the dataset)
#define BB 4
#define CC 32
#define HH 64
#define WW 64
#define KK 64
#define HW 4096          // H*W
#define CAPK 1152        // max nnz per RF (disk r<=17.2 -> <=~1030)

// ---------- static device scratch (no allocations allowed) ----------
// k-major packed: {rf value, pixel index as float-bits}
__device__ float2 g_kpack[KK * CAPK];
__device__ int    g_knnz [KK];
// pixel-major packed: {rf value, k as float-bits}, layout [j][px]
__device__ float2 g_ppack[KK * HW];
__device__ int    g_pcnt [HW];

// ============================================================================
// Prep kernel: 80 blocks x 256 threads.
//   blocks 0..63  : k-major compaction of rfs[k] (deterministic order)
//   blocks 64..79 : pixel-major compaction (deterministic k order per pixel)
// ============================================================================
__global__ void rf_prep_kernel(const float* __restrict__ rfs)
{
    int tid = threadIdx.x;
    if (blockIdx.x < KK) {
        // ---- k-major compaction for k = blockIdx.x ----
        int k = blockIdx.x;
        const float* r = rfs + k * HW;
        __shared__ int s[256];
        int px0 = tid * 16;
        int cnt = 0;
        #pragma unroll
        for (int j = 0; j < 16; j++) cnt += (r[px0 + j] > 0.0f);
        s[tid] = cnt;
        __syncthreads();
        // inclusive Hillis-Steele scan over 256
        for (int off = 1; off < 256; off <<= 1) {
            int add = (tid >= off) ? s[tid - off] : 0;
            __syncthreads();
            s[tid] += add;
            __syncthreads();
        }
        int off = s[tid] - cnt;            // exclusive offset
        int total = s[255];
        float2* kp = g_kpack + k * CAPK;
        #pragma unroll
        for (int j = 0; j < 16; j++) {
            float g = r[px0 + j];
            if (g > 0.0f) {
                if (off < CAPK) {
                    float2 e; e.x = g; e.y = __int_as_float(px0 + j);
                    kp[off] = e;
                }
                off++;
            }
        }
        if (tid == 0) g_knnz[k] = (total < CAPK) ? total : CAPK;
    } else {
        // ---- pixel-major compaction ----
        int px = (blockIdx.x - KK) * 256 + tid;   // 16 blocks x 256 = 4096
        int cnt = 0;
        #pragma unroll 8
        for (int k = 0; k < KK; k++) {
            float g = rfs[k * HW + px];           // coalesced across lanes
            if (g > 0.0f) {
                float2 e; e.x = g; e.y = __int_as_float(k);
                g_ppack[cnt * HW + px] = e;
                cnt++;
            }
        }
        g_pcnt[px] = cnt;
    }
}

// ============================================================================
// Main kernel: one block per (b,c) image. 1024 threads = 32 warps.
//   Phase A: per-k denominators via warp reductions (k-major lists)
//   Phase B: per-pixel h accumulation (pixel-major lists, race-free)
//   Phase C: 2x2 block-max pooling, write output
// ============================================================================
__global__ void __launch_bounds__(1024, 1)
rf_pool_main_kernel(const float* __restrict__ u, float* __restrict__ out)
{
    __shared__ float u_s[HW];     // 16 KB
    __shared__ float h_s[HW];     // 16 KB
    __shared__ float invd_s[KK];  // 256 B

    int tid  = threadIdx.x;
    int warp = tid >> 5;          // 0..31
    int lane = tid & 31;

    // load this image into smem (coalesced float4: 1024 * 16B = 16KB)
    ((float4*)u_s)[tid] = ((const float4*)(u + (size_t)blockIdx.x * HW))[tid];
    __syncthreads();

    // ---- Phase A: invd[k] = 1 / (1 + sum_supp exp(u*rf)) ----
    #pragma unroll
    for (int kk = 0; kk < KK; kk += 32) {
        int k = warp + kk;
        int n = g_knnz[k];
        const float2* kp = g_kpack + k * CAPK;
        float s = 0.0f;
        #pragma unroll 4
        for (int i = lane; i < n; i += 32) {
            float2 e = kp[i];
            s += __expf(u_s[__float_as_int(e.y)] * e.x);
        }
        #pragma unroll
        for (int o = 16; o; o >>= 1) s += __shfl_xor_sync(0xffffffffu, s, o);
        if (lane == 0) invd_s[k] = 1.0f / (1.0f + s);
    }
    __syncthreads();

    // ---- Phase B: h[px] = sum_j exp(u[px]*val_j) * invd[k_j] ----
    #pragma unroll
    for (int r = 0; r < HW / 1024; r++) {
        int px = tid + r * 1024;
        float uv = u_s[px];
        int  cnt = g_pcnt[px];
        float h = 0.0f;
        #pragma unroll 4
        for (int j = 0; j < cnt; j++) {
            float2 e = g_ppack[j * HW + px];   // coalesced across lanes
            h += __expf(uv * e.x) * invd_s[__float_as_int(e.y)];
        }
        h_s[px] = h;
    }
    __syncthreads();

    // ---- Phase C: 2x2 block max -> 32x32 outputs (1 per thread) ----
    float* o = out + (size_t)blockIdx.x * 1024;
    int oy = tid >> 5, ox = tid & 31;
    int p0 = (oy * 2) * WW + ox * 2;
    float m = fmaxf(fmaxf(h_s[p0], h_s[p0 + 1]),
                    fmaxf(h_s[p0 + WW], h_s[p0 + WW + 1]));
    o[tid] = m;
}

// ============================================================================
extern "C" void kernel_launch(void* const* d_in, const int* in_sizes, int n_in,
                              void* d_out, int out_size)
{
    // inputs: u (4*32*64*64 = 524288 f32), rfs (64*64*64 = 262144 f32)
    const float* u   = (const float*)d_in[0];
    const float* rfs = (const float*)d_in[1];
    if (n_in >= 2 && in_sizes[0] == KK * HW && in_sizes[1] == BB * CC * HW) {
        // defensive: swapped order
        const float* t = u; u = rfs; rfs = t;
    }
    float* out = (float*)d_out;

    rf_prep_kernel<<<KK + HW / 256, 256>>>(rfs);
    rf_pool_main_kernel<<<BB * CC, 1024>>>(u, out);
}